// round 6
// baseline (speedup 1.0000x reference)
#include <cuda_runtime.h>
#include <cuda_fp16.h>
#include <math.h>

// Problem constants
#define NB    16
#define NDIM  256
#define SS    64
#define NHEADS 4
#define HD    16
#define NPIX  4096
#define NBB   64

// ---------------- scratch ----------
// packed hi/lo fp16 pairs (hi in low 16 bits, lo in high 16 bits)
__device__ unsigned g_yhl[(size_t)NB * NDIM * NPIX];
__device__ float    g_qkv[(size_t)NBB * 192 * NPIX];
__device__ float    g_M[4096];
__device__ float    g_Z[4096];
__device__ float    g_ctx[(size_t)NBB * NHEADS * HD * HD];
__device__ unsigned g_aohl[(size_t)NBB * SS * NPIX];
__device__ unsigned g_cathl[(size_t)NB * NDIM * NPIX];

// ---------------- helpers ----------
__device__ __forceinline__ unsigned pack_h2(__half a, __half b) {
    return (unsigned)__half_as_ushort(a) | ((unsigned)__half_as_ushort(b) << 16);
}
__device__ __forceinline__ unsigned packhl(float v) {
    __half h = __float2half_rn(v);
    __half l = __float2half_rn(v - __half2float(h));
    return pack_h2(h, l);
}
__device__ __forceinline__ void mma16816(float* d, const unsigned* a, const unsigned* b) {
    asm volatile(
        "mma.sync.aligned.m16n8k16.row.col.f32.f16.f16.f32 "
        "{%0,%1,%2,%3}, {%4,%5,%6,%7}, {%8,%9}, {%0,%1,%2,%3};"
        : "+f"(d[0]), "+f"(d[1]), "+f"(d[2]), "+f"(d[3])
        : "r"(a[0]), "r"(a[1]), "r"(a[2]), "r"(a[3]), "r"(b[0]), "r"(b[1]));
}

// ---------------- depthwise conv + bias + residual + relu -----------------
__global__ __launch_bounds__(256) void dwconv_kernel(
    const float* __restrict__ x,
    const float* __restrict__ w3, const float* __restrict__ b3,
    const float* __restrict__ w5, const float* __restrict__ b5,
    const float* __restrict__ w7, const float* __restrict__ b7,
    const float* __restrict__ w9, const float* __restrict__ b9)
{
    __shared__ float s[4096];
    __shared__ float ws[81];
    int bc = blockIdx.x;
    int cg = bc & 255;
    int br = cg >> 6;
    int c  = cg & 63;
    const float* wsrc; const float* bsrc; int k;
    if (br == 0)      { wsrc = w3; bsrc = b3; k = 3; }
    else if (br == 1) { wsrc = w5; bsrc = b5; k = 5; }
    else if (br == 2) { wsrc = w7; bsrc = b7; k = 7; }
    else              { wsrc = w9; bsrc = b9; k = 9; }
    int t = threadIdx.x;
    const float* xp = x + (size_t)bc * NPIX;
    #pragma unroll
    for (int i = 0; i < 16; i++) s[t + i * 256] = xp[t + i * 256];
    if (t < k * k) ws[t] = wsrc[c * k * k + t];
    float bv = bsrc[c];
    __syncthreads();
    int r = k >> 1;
    for (int i = 0; i < 16; i++) {
        int p  = t + i * 256;
        int py = p >> 6, px = p & 63;
        float acc = 0.f;
        for (int u = 0; u < k; u++) {
            int yy = py + u - r;
            if ((unsigned)yy >= 64u) continue;
            const float* srow = &s[yy * 64];
            const float* wrow = &ws[u * k];
            for (int v = 0; v < k; v++) {
                int xx = px + v - r;
                if ((unsigned)xx >= 64u) continue;
                acc += srow[xx] * wrow[v];
            }
        }
        float o = fmaxf(acc + bv + s[p], 0.f);
        g_yhl[(size_t)bc * NPIX + p] = packhl(o);
    }
}

// ---------------- tensor-core GEMM, A pre-split packed hi/lo --------------
// C(m,j) = sum_k A(m,k) * W(j,k);  A packed-hl: [chunk][k*4096 + m], W fp32 [j*K + k]
// CTA tile 128(m) x 64(j), K-step 32, 256 threads = 8 warps (4 m x 2 j).
// grid: (jTiles, mTiles)  -- j fast-varying for L2 reuse of A.
// Epilogue staged through smem for coalesced float4/uint4 stores.
#define SAH 40   // smem row stride in halves
__global__ __launch_bounds__(256) void gemm_tc(
    const unsigned* __restrict__ A, const float* __restrict__ W,
    const float* __restrict__ bias, const float* __restrict__ scalew,
    float* __restrict__ C, int K, long chunkA, long chunkC, int packout)
{
    __shared__ __align__(16) char smraw[30720];
    __half (*Ah)[SAH] = (__half(*)[SAH])(smraw);
    __half (*Al)[SAH] = (__half(*)[SAH])(smraw + 10240);
    __half (*Wh)[SAH] = (__half(*)[SAH])(smraw + 20480);
    __half (*Wl)[SAH] = (__half(*)[SAH])(smraw + 25600);
    float (*stage)[132] = (float(*)[132])(smraw);   // 32x132 floats = 16896 B (reused)

    int j0    = blockIdx.x * 64;
    int m0    = blockIdx.y * 128;
    int chunk = m0 >> 12;
    int mloc  = m0 & 4095;

    const unsigned* Ab = A + (size_t)chunk * chunkA + mloc;
    const float*    Wb = W + (size_t)j0 * K;
    float*          Cb = C + (size_t)chunk * chunkC + mloc + (size_t)j0 * 4096;
    float scale = scalew ? scalew[chunk & 3] : 1.0f;

    int tid  = threadIdx.x;
    int wp   = tid >> 5;
    int lane = tid & 31;
    int g = lane >> 2, t4 = lane & 3;
    int warpm = wp & 3;
    int warpj = wp >> 2;

    int jf = tid >> 2;          // 0..63
    int kf = (tid & 3) * 8;     // 0,8,16,24

    float acc[2][4][4];
    #pragma unroll
    for (int mi = 0; mi < 2; mi++)
        #pragma unroll
        for (int ji = 0; ji < 4; ji++)
            #pragma unroll
            for (int cc = 0; cc < 4; cc++) acc[mi][ji][cc] = 0.f;

    for (int k0 = 0; k0 < K; k0 += 32) {
        // ---- fill W (hi/lo) from fp32 ----
        {
            float4 w0 = *(const float4*)(Wb + (size_t)jf * K + k0 + kf);
            float4 w1 = *(const float4*)(Wb + (size_t)jf * K + k0 + kf + 4);
            float v[8] = {w0.x, w0.y, w0.z, w0.w, w1.x, w1.y, w1.z, w1.w};
            __half hh[8], hl[8];
            #pragma unroll
            for (int i = 0; i < 8; i++) {
                hh[i] = __float2half_rn(v[i]);
                hl[i] = __float2half_rn(v[i] - __half2float(hh[i]));
            }
            uint4 uh, ul;
            uh.x = pack_h2(hh[0], hh[1]); uh.y = pack_h2(hh[2], hh[3]);
            uh.z = pack_h2(hh[4], hh[5]); uh.w = pack_h2(hh[6], hh[7]);
            ul.x = pack_h2(hl[0], hl[1]); ul.y = pack_h2(hl[2], hl[3]);
            ul.z = pack_h2(hl[4], hl[5]); ul.w = pack_h2(hl[6], hl[7]);
            *(uint4*)&Wh[jf][kf] = uh;
            *(uint4*)&Wl[jf][kf] = ul;
        }
        // ---- fill A: load packed hi/lo, byte-perm split, transpose -> [m][k]
        {
            int kb = wp * 4;
            #pragma unroll
            for (int c = 0; c < 4; c++) {
                int m = c * 32 + lane;
                unsigned u[4];
                #pragma unroll
                for (int i = 0; i < 4; i++)
                    u[i] = Ab[(size_t)(k0 + kb + i) * 4096 + m];
                uint2 uh, ul;
                uh.x = __byte_perm(u[0], u[1], 0x5410);
                uh.y = __byte_perm(u[2], u[3], 0x5410);
                ul.x = __byte_perm(u[0], u[1], 0x7632);
                ul.y = __byte_perm(u[2], u[3], 0x7632);
                *(uint2*)&Ah[m][kb] = uh;
                *(uint2*)&Al[m][kb] = ul;
            }
        }
        __syncthreads();

        // ---- compute: two k16 sub-steps ----
        #pragma unroll
        for (int kk = 0; kk < 32; kk += 16) {
            unsigned ah[2][4], al[2][4];
            #pragma unroll
            for (int mi = 0; mi < 2; mi++) {
                int row = warpm * 32 + mi * 16 + g;
                ah[mi][0] = *(const unsigned*)&Ah[row    ][kk + 2 * t4];
                ah[mi][1] = *(const unsigned*)&Ah[row + 8][kk + 2 * t4];
                ah[mi][2] = *(const unsigned*)&Ah[row    ][kk + 2 * t4 + 8];
                ah[mi][3] = *(const unsigned*)&Ah[row + 8][kk + 2 * t4 + 8];
                al[mi][0] = *(const unsigned*)&Al[row    ][kk + 2 * t4];
                al[mi][1] = *(const unsigned*)&Al[row + 8][kk + 2 * t4];
                al[mi][2] = *(const unsigned*)&Al[row    ][kk + 2 * t4 + 8];
                al[mi][3] = *(const unsigned*)&Al[row + 8][kk + 2 * t4 + 8];
            }
            unsigned bh[4][2], bl[4][2];
            #pragma unroll
            for (int ji = 0; ji < 4; ji++) {
                int j = warpj * 32 + ji * 8 + g;
                bh[ji][0] = *(const unsigned*)&Wh[j][kk + 2 * t4];
                bh[ji][1] = *(const unsigned*)&Wh[j][kk + 2 * t4 + 8];
                bl[ji][0] = *(const unsigned*)&Wl[j][kk + 2 * t4];
                bl[ji][1] = *(const unsigned*)&Wl[j][kk + 2 * t4 + 8];
            }
            #pragma unroll
            for (int mi = 0; mi < 2; mi++)
                #pragma unroll
                for (int ji = 0; ji < 4; ji++) {
                    mma16816(acc[mi][ji], ah[mi], bh[ji]);
                    mma16816(acc[mi][ji], ah[mi], bl[ji]);
                    mma16816(acc[mi][ji], al[mi], bh[ji]);
                }
        }
        __syncthreads();
    }

    // ---- staged epilogue: smem transpose -> coalesced stores along m ----
    unsigned* Cp = (unsigned*)Cb;
    #pragma unroll
    for (int p = 0; p < 2; p++) {
        if (warpj == p) {
            #pragma unroll
            for (int mi = 0; mi < 2; mi++)
                #pragma unroll
                for (int ji = 0; ji < 4; ji++) {
                    int jr = ji * 8 + 2 * t4;             // 0..30
                    int m  = warpm * 32 + mi * 16 + g;
                    stage[jr    ][m    ] = acc[mi][ji][0];
                    stage[jr + 1][m    ] = acc[mi][ji][1];
                    stage[jr    ][m + 8] = acc[mi][ji][2];
                    stage[jr + 1][m + 8] = acc[mi][ji][3];
                }
        }
        __syncthreads();
        #pragma unroll
        for (int r = 0; r < 4; r++) {
            int idx = r * 256 + tid;     // 0..1023
            int jr  = idx >> 5;          // 0..31
            int m4  = (idx & 31) * 4;
            int jg  = p * 32 + jr;
            float bj = bias ? bias[j0 + jg] : 0.f;
            float4 v = *(const float4*)&stage[jr][m4];
            v.x = (v.x + bj) * scale;
            v.y = (v.y + bj) * scale;
            v.z = (v.z + bj) * scale;
            v.w = (v.w + bj) * scale;
            if (packout) {
                uint4 u;
                u.x = packhl(v.x); u.y = packhl(v.y);
                u.z = packhl(v.z); u.w = packhl(v.w);
                *(uint4*)(Cp + (size_t)jg * 4096 + m4) = u;
            } else {
                *(float4*)(Cb + (size_t)jg * 4096 + m4) = v;
            }
        }
        __syncthreads();
    }
}

// ---------------- softmax over hd=16 on K (in place) ----------------------
__global__ __launch_bounds__(256) void ksoftmax_kernel()
{
    int idx = blockIdx.x * 256 + threadIdx.x;
    int n  = idx & 4095;
    int hh = idx >> 12;
    int bb = hh >> 2, h = hh & 3;
    float* base = g_qkv + ((size_t)(bb * 192 + 64 + h * 16)) * 4096 + n;
    float v[16];
    float mx = -3.4e38f;
    #pragma unroll
    for (int d = 0; d < 16; d++) { v[d] = base[(size_t)d * 4096]; mx = fmaxf(mx, v[d]); }
    float ssum = 0.f;
    #pragma unroll
    for (int d = 0; d < 16; d++) { v[d] = __expf(v[d] - mx); ssum += v[d]; }
    float inv = 1.0f / ssum;
    #pragma unroll
    for (int d = 0; d < 16; d++) base[(size_t)d * 4096] = v[d] * inv;
}

// ---------------- column stats (max, sumexp) over n for Q -----------------
__global__ __launch_bounds__(256) void qstats_kernel()
{
    __shared__ float red[256];
    int col = blockIdx.x;
    int bb = col >> 6, j = col & 63;
    const float* base = g_qkv + ((size_t)(bb * 192 + j)) * 4096;
    int t = threadIdx.x;
    float v[16];
    float mx = -3.4e38f;
    #pragma unroll
    for (int i = 0; i < 16; i++) { v[i] = base[t + i * 256]; mx = fmaxf(mx, v[i]); }
    red[t] = mx; __syncthreads();
    for (int s2 = 128; s2 > 0; s2 >>= 1) {
        if (t < s2) red[t] = fmaxf(red[t], red[t + s2]);
        __syncthreads();
    }
    mx = red[0]; __syncthreads();
    float sum = 0.f;
    #pragma unroll
    for (int i = 0; i < 16; i++) sum += __expf(v[i] - mx);
    red[t] = sum; __syncthreads();
    for (int s2 = 128; s2 > 0; s2 >>= 1) {
        if (t < s2) red[t] += red[t + s2];
        __syncthreads();
    }
    if (t == 0) { g_M[col] = mx; g_Z[col] = red[0]; }
}

// ---------------- context: C[d,e] = sum_n key[n,d] v[n,e], / Z ------------
__global__ __launch_bounds__(256) void context_kernel()
{
    __shared__ float ks[16][128];
    __shared__ float vs[16][128];
    int bh = blockIdx.x;
    int bb = bh >> 2, h = bh & 3;
    const float* kb = g_qkv + ((size_t)(bb * 192 + 64  + h * 16)) * 4096;
    const float* vb = g_qkv + ((size_t)(bb * 192 + 128 + h * 16)) * 4096;
    int t = threadIdx.x;
    int d = t >> 4, e = t & 15;
    float acc = 0.f;
    for (int n0 = 0; n0 < 4096; n0 += 128) {
        #pragma unroll
        for (int i = 0; i < 2; i++) {
            int idx = t * 2 + i;
            int row = idx >> 5;
            int c4  = (idx & 31) * 4;
            *(float4*)&ks[row][c4] = *(const float4*)(kb + (size_t)row * 4096 + n0 + c4);
            *(float4*)&vs[row][c4] = *(const float4*)(vb + (size_t)row * 4096 + n0 + c4);
        }
        __syncthreads();
        #pragma unroll
        for (int q4 = 0; q4 < 32; q4++) {
            float4 a = *(const float4*)&ks[d][q4 * 4];
            float4 b = *(const float4*)&vs[e][q4 * 4];
            acc += a.x * b.x + a.y * b.y + a.z * b.z + a.w * b.w;
        }
        __syncthreads();
    }
    float z = g_Z[bb * 64 + h * 16 + d];
    g_ctx[(size_t)bh * 256 + d * 16 + e] = acc / z;
}

// ---------------- attn out: ao = exp(q-M) @ ctx, reference reshape folded:
//   pixel  n' = h*1024 + (n>>2),  chan c' = 16*(n&3) + e ; packed hi/lo out
__global__ __launch_bounds__(256) void attnout_kernel()
{
    __shared__ float cs[1024];
    __shared__ float ms[64];
    int bb = blockIdx.x >> 4;
    int nt = blockIdx.x & 15;
    int t  = threadIdx.x;
    int n  = nt * 256 + t;
    if (t < 64) ms[t] = g_M[bb * 64 + t];
    for (int i = t; i < 1024; i += 256) cs[i] = g_ctx[(size_t)bb * 1024 + i];
    __syncthreads();
    const float* qb = g_qkv + (size_t)bb * 192 * 4096 + n;
    int cbase = 16 * (n & 3);
    int pbase = n >> 2;
    for (int h = 0; h < 4; h++) {
        float acc[16];
        #pragma unroll
        for (int e = 0; e < 16; e++) acc[e] = 0.f;
        #pragma unroll
        for (int d = 0; d < 16; d++) {
            int jc = h * 16 + d;
            float qv = __expf(qb[(size_t)jc * 4096] - ms[jc]);
            const float4* crow = (const float4*)&cs[jc * 16];
            #pragma unroll
            for (int e4 = 0; e4 < 4; e4++) {
                float4 cv = crow[e4];
                acc[e4 * 4 + 0] += qv * cv.x;
                acc[e4 * 4 + 1] += qv * cv.y;
                acc[e4 * 4 + 2] += qv * cv.z;
                acc[e4 * 4 + 3] += qv * cv.w;
            }
        }
        int np = h * 1024 + pbase;
        #pragma unroll
        for (int e = 0; e < 16; e++)
            g_aohl[((size_t)(bb * 64 + cbase + e)) * 4096 + np] = packhl(acc[e]);
    }
}

// ---------------- launch ---------------------------------------------------
extern "C" void kernel_launch(void* const* d_in, const int* in_sizes, int n_in,
                              void* d_out, int out_size)
{
    const float* x   = (const float*)d_in[0];
    const float* w3  = (const float*)d_in[1];
    const float* b3  = (const float*)d_in[2];
    const float* w5  = (const float*)d_in[3];
    const float* b5  = (const float*)d_in[4];
    const float* w7  = (const float*)d_in[5];
    const float* b7  = (const float*)d_in[6];
    const float* w9  = (const float*)d_in[7];
    const float* b9  = (const float*)d_in[8];
    const float* w_qkv   = (const float*)d_in[9];
    const float* w_proj  = (const float*)d_in[10];
    const float* b_proj  = (const float*)d_in[11];
    const float* w_final = (const float*)d_in[12];
    const float* b_final = (const float*)d_in[13];
    const float* scale_w = (const float*)d_in[14];
    float* out = (float*)d_out;

    unsigned *yp, *aop, *catp;
    float *qkvp;
    cudaGetSymbolAddress((void**)&yp,   g_yhl);
    cudaGetSymbolAddress((void**)&qkvp, g_qkv);
    cudaGetSymbolAddress((void**)&aop,  g_aohl);
    cudaGetSymbolAddress((void**)&catp, g_cathl);

    // 1. depthwise conv + bias + residual + relu  -> g_yhl (packed hi/lo)
    dwconv_kernel<<<NB * NDIM, 256>>>(x, w3, b3, w5, b5, w7, b7, w9, b9);

    // 2. QKV GEMM -> g_qkv (fp32)   grid (j,m) - j fast for L2 A-reuse
    gemm_tc<<<dim3(3, 262144 / 128), 256>>>(yp, w_qkv, nullptr, nullptr, qkvp,
                                            64, 64L * 4096, 192L * 4096, 0);

    // 3. softmax over hd for K (in place)
    ksoftmax_kernel<<<4096, 256>>>();

    // 4. column stats for Q softmax
    qstats_kernel<<<4096, 256>>>();

    // 5. context = key^T v, folded / Z
    context_kernel<<<256, 256>>>();

    // 6. attention out -> g_aohl (packed hi/lo, scrambled reshape layout)
    attnout_kernel<<<1024, 256>>>();

    // 7. proj GEMM + bias + branch scale -> g_cathl (packed hi/lo)
    gemm_tc<<<dim3(1, 262144 / 128), 256>>>(aop, w_proj, b_proj, scale_w,
                                            (float*)catp,
                                            64, 64L * 4096, 64L * 4096, 1);

    // 8. final 1x1 conv -> d_out (fp32)
    gemm_tc<<<dim3(4, 65536 / 128), 256>>>(catp, w_final, b_final, nullptr, out,
                                           256, 256L * 4096, 256L * 4096, 0);
}

// round 7
// speedup vs baseline: 1.1054x; 1.1054x over previous
#include <cuda_runtime.h>
#include <cuda_fp16.h>
#include <math.h>

// Problem constants
#define NB    16
#define NDIM  256
#define SS    64
#define NHEADS 4
#define HD    16
#define NPIX  4096
#define NBB   64

// ---------------- scratch ----------
__device__ unsigned g_yhl[(size_t)NB * NDIM * NPIX];    // packed hi/lo fp16
__device__ float    g_qkv[(size_t)NBB * 192 * NPIX];    // q raw, k softmaxed, v
__device__ float    g_M[4096];
__device__ float    g_Z[4096];
__device__ float    g_ctx[(size_t)NBB * NHEADS * HD * HD];
__device__ unsigned g_aohl[(size_t)NBB * SS * NPIX];    // packed hi/lo, scrambled layout
__device__ float    g_wc[256 * 256];                    // fused proj+final weight
__device__ float    g_cb[256];                          // fused bias

// ---------------- helpers ----------
__device__ __forceinline__ unsigned pack_h2(__half a, __half b) {
    return (unsigned)__half_as_ushort(a) | ((unsigned)__half_as_ushort(b) << 16);
}
__device__ __forceinline__ unsigned packhl(float v) {
    __half h = __float2half_rn(v);
    __half l = __float2half_rn(v - __half2float(h));
    return pack_h2(h, l);
}
__device__ __forceinline__ void mma16816(float* d, const unsigned* a, const unsigned* b) {
    asm volatile(
        "mma.sync.aligned.m16n8k16.row.col.f32.f16.f16.f32 "
        "{%0,%1,%2,%3}, {%4,%5,%6,%7}, {%8,%9}, {%0,%1,%2,%3};"
        : "+f"(d[0]), "+f"(d[1]), "+f"(d[2]), "+f"(d[3])
        : "r"(a[0]), "r"(a[1]), "r"(a[2]), "r"(a[3]), "r"(b[0]), "r"(b[1]));
}

// ---------------- weight-fusion prep: Wc = scale * Wf @ Wp,  cbias --------
__global__ __launch_bounds__(256) void wcprep_kernel(
    const float* __restrict__ wp, const float* __restrict__ wf,
    const float* __restrict__ bp, const float* __restrict__ bf,
    const float* __restrict__ sw)
{
    __shared__ float sWf[256];
    __shared__ float red[256];
    int co = blockIdx.x;
    int t  = threadIdx.x;           // cc = br*64 + e
    sWf[t] = wf[co * 256 + t];
    __syncthreads();
    int br = t >> 6, e = t & 63;
    float s = sw[br];
    float acc = 0.f;
    #pragma unroll 8
    for (int ci = 0; ci < 64; ci++)
        acc += sWf[br * 64 + ci] * wp[ci * 64 + e];
    g_wc[co * 256 + t] = acc * s;
    red[t] = s * sWf[t] * bp[e];
    __syncthreads();
    for (int s2 = 128; s2 > 0; s2 >>= 1) {
        if (t < s2) red[t] += red[t + s2];
        __syncthreads();
    }
    if (t == 0) g_cb[co] = bf[co] + red[0];
}

// ---------------- depthwise conv + bias + residual + relu -----------------
__global__ __launch_bounds__(256) void dwconv_kernel(
    const float* __restrict__ x,
    const float* __restrict__ w3, const float* __restrict__ b3,
    const float* __restrict__ w5, const float* __restrict__ b5,
    const float* __restrict__ w7, const float* __restrict__ b7,
    const float* __restrict__ w9, const float* __restrict__ b9)
{
    __shared__ float s[4096];
    __shared__ float ws[81];
    int bc = blockIdx.x;
    int cg = bc & 255;
    int br = cg >> 6;
    int c  = cg & 63;
    const float* wsrc; const float* bsrc; int k;
    if (br == 0)      { wsrc = w3; bsrc = b3; k = 3; }
    else if (br == 1) { wsrc = w5; bsrc = b5; k = 5; }
    else if (br == 2) { wsrc = w7; bsrc = b7; k = 7; }
    else              { wsrc = w9; bsrc = b9; k = 9; }
    int t = threadIdx.x;
    const float* xp = x + (size_t)bc * NPIX;
    #pragma unroll
    for (int i = 0; i < 16; i++) s[t + i * 256] = xp[t + i * 256];
    if (t < k * k) ws[t] = wsrc[c * k * k + t];
    float bv = bsrc[c];
    __syncthreads();
    int r = k >> 1;
    for (int i = 0; i < 16; i++) {
        int p  = t + i * 256;
        int py = p >> 6, px = p & 63;
        float acc = 0.f;
        for (int u = 0; u < k; u++) {
            int yy = py + u - r;
            if ((unsigned)yy >= 64u) continue;
            const float* srow = &s[yy * 64];
            const float* wrow = &ws[u * k];
            for (int v = 0; v < k; v++) {
                int xx = px + v - r;
                if ((unsigned)xx >= 64u) continue;
                acc += srow[xx] * wrow[v];
            }
        }
        float o = fmaxf(acc + bv + s[p], 0.f);
        g_yhl[(size_t)bc * NPIX + p] = packhl(o);
    }
}

// ---------------- tensor-core GEMM, A pre-split packed hi/lo --------------
// C(m,j) = sum_k A(m,k) * W(j,k);  A packed-hl: [chunk][k*4096 + m], W fp32 [j*K + k]
// CTA tile 128(m) x 64(j), K-step 32, 256 threads = 8 warps (4 m x 2 j).
// grid: (jTiles, mTiles). Staged epilogue; optional fused hd-softmax for the
// K block of the qkv GEMM (j0 == 64): softmax over each 16-wide head group.
#define SAH 40
__global__ __launch_bounds__(256) void gemm_tc(
    const unsigned* __restrict__ A, const float* __restrict__ W,
    const float* __restrict__ bias,
    float* __restrict__ C, int K, long chunkA, long chunkC, int dosoftmax)
{
    __shared__ __align__(16) char smraw[30720];
    __half (*Ah)[SAH] = (__half(*)[SAH])(smraw);
    __half (*Al)[SAH] = (__half(*)[SAH])(smraw + 10240);
    __half (*Wh)[SAH] = (__half(*)[SAH])(smraw + 20480);
    __half (*Wl)[SAH] = (__half(*)[SAH])(smraw + 25600);
    float (*stage)[132] = (float(*)[132])(smraw);   // reused after mainloop

    int j0    = blockIdx.x * 64;
    int m0    = blockIdx.y * 128;
    int chunk = m0 >> 12;
    int mloc  = m0 & 4095;

    const unsigned* Ab = A + (size_t)chunk * chunkA + mloc;
    const float*    Wb = W + (size_t)j0 * K;
    float*          Cb = C + (size_t)chunk * chunkC + mloc + (size_t)j0 * 4096;

    int tid  = threadIdx.x;
    int wp   = tid >> 5;
    int lane = tid & 31;
    int g = lane >> 2, t4 = lane & 3;
    int warpm = wp & 3;
    int warpj = wp >> 2;

    int jf = tid >> 2;
    int kf = (tid & 3) * 8;

    float acc[2][4][4];
    #pragma unroll
    for (int mi = 0; mi < 2; mi++)
        #pragma unroll
        for (int ji = 0; ji < 4; ji++)
            #pragma unroll
            for (int cc = 0; cc < 4; cc++) acc[mi][ji][cc] = 0.f;

    for (int k0 = 0; k0 < K; k0 += 32) {
        {   // W fill (hi/lo from fp32)
            float4 w0 = *(const float4*)(Wb + (size_t)jf * K + k0 + kf);
            float4 w1 = *(const float4*)(Wb + (size_t)jf * K + k0 + kf + 4);
            float v[8] = {w0.x, w0.y, w0.z, w0.w, w1.x, w1.y, w1.z, w1.w};
            __half hh[8], hl[8];
            #pragma unroll
            for (int i = 0; i < 8; i++) {
                hh[i] = __float2half_rn(v[i]);
                hl[i] = __float2half_rn(v[i] - __half2float(hh[i]));
            }
            uint4 uh, ul;
            uh.x = pack_h2(hh[0], hh[1]); uh.y = pack_h2(hh[2], hh[3]);
            uh.z = pack_h2(hh[4], hh[5]); uh.w = pack_h2(hh[6], hh[7]);
            ul.x = pack_h2(hl[0], hl[1]); ul.y = pack_h2(hl[2], hl[3]);
            ul.z = pack_h2(hl[4], hl[5]); ul.w = pack_h2(hl[6], hl[7]);
            *(uint4*)&Wh[jf][kf] = uh;
            *(uint4*)&Wl[jf][kf] = ul;
        }
        {   // A fill: packed hi/lo -> byte-perm split -> [m][k]
            int kb = wp * 4;
            #pragma unroll
            for (int c = 0; c < 4; c++) {
                int m = c * 32 + lane;
                unsigned u[4];
                #pragma unroll
                for (int i = 0; i < 4; i++)
                    u[i] = Ab[(size_t)(k0 + kb + i) * 4096 + m];
                uint2 uh, ul;
                uh.x = __byte_perm(u[0], u[1], 0x5410);
                uh.y = __byte_perm(u[2], u[3], 0x5410);
                ul.x = __byte_perm(u[0], u[1], 0x7632);
                ul.y = __byte_perm(u[2], u[3], 0x7632);
                *(uint2*)&Ah[m][kb] = uh;
                *(uint2*)&Al[m][kb] = ul;
            }
        }
        __syncthreads();

        #pragma unroll
        for (int kk = 0; kk < 32; kk += 16) {
            unsigned ah[2][4], al[2][4];
            #pragma unroll
            for (int mi = 0; mi < 2; mi++) {
                int row = warpm * 32 + mi * 16 + g;
                ah[mi][0] = *(const unsigned*)&Ah[row    ][kk + 2 * t4];
                ah[mi][1] = *(const unsigned*)&Ah[row + 8][kk + 2 * t4];
                ah[mi][2] = *(const unsigned*)&Ah[row    ][kk + 2 * t4 + 8];
                ah[mi][3] = *(const unsigned*)&Ah[row + 8][kk + 2 * t4 + 8];
                al[mi][0] = *(const unsigned*)&Al[row    ][kk + 2 * t4];
                al[mi][1] = *(const unsigned*)&Al[row + 8][kk + 2 * t4];
                al[mi][2] = *(const unsigned*)&Al[row    ][kk + 2 * t4 + 8];
                al[mi][3] = *(const unsigned*)&Al[row + 8][kk + 2 * t4 + 8];
            }
            unsigned bh[4][2], bl[4][2];
            #pragma unroll
            for (int ji = 0; ji < 4; ji++) {
                int j = warpj * 32 + ji * 8 + g;
                bh[ji][0] = *(const unsigned*)&Wh[j][kk + 2 * t4];
                bh[ji][1] = *(const unsigned*)&Wh[j][kk + 2 * t4 + 8];
                bl[ji][0] = *(const unsigned*)&Wl[j][kk + 2 * t4];
                bl[ji][1] = *(const unsigned*)&Wl[j][kk + 2 * t4 + 8];
            }
            #pragma unroll
            for (int mi = 0; mi < 2; mi++)
                #pragma unroll
                for (int ji = 0; ji < 4; ji++) {
                    mma16816(acc[mi][ji], ah[mi], bh[ji]);
                    mma16816(acc[mi][ji], ah[mi], bl[ji]);
                    mma16816(acc[mi][ji], al[mi], bh[ji]);
                }
        }
        __syncthreads();
    }

    // ---- staged epilogue ----
    int ksoft = dosoftmax && (j0 == 64);
    #pragma unroll
    for (int p = 0; p < 2; p++) {
        if (warpj == p) {
            #pragma unroll
            for (int mi = 0; mi < 2; mi++)
                #pragma unroll
                for (int ji = 0; ji < 4; ji++) {
                    int jr = ji * 8 + 2 * t4;
                    int m  = warpm * 32 + mi * 16 + g;
                    stage[jr    ][m    ] = acc[mi][ji][0];
                    stage[jr + 1][m    ] = acc[mi][ji][1];
                    stage[jr    ][m + 8] = acc[mi][ji][2];
                    stage[jr + 1][m + 8] = acc[mi][ji][3];
                }
        }
        __syncthreads();
        if (ksoft) {
            // softmax over each 16-row head group (2 heads per phase)
            int hh = tid >> 7;          // 0..1
            int m  = tid & 127;
            float v[16];
            float mx = -3.4e38f;
            #pragma unroll
            for (int d = 0; d < 16; d++) { v[d] = stage[hh * 16 + d][m]; mx = fmaxf(mx, v[d]); }
            float ssum = 0.f;
            #pragma unroll
            for (int d = 0; d < 16; d++) { v[d] = __expf(v[d] - mx); ssum += v[d]; }
            float inv = 1.0f / ssum;
            #pragma unroll
            for (int d = 0; d < 16; d++)
                Cb[(size_t)(p * 32 + hh * 16 + d) * 4096 + m] = v[d] * inv;
        } else {
            #pragma unroll
            for (int r = 0; r < 4; r++) {
                int idx = r * 256 + tid;
                int jr  = idx >> 5;
                int m4  = (idx & 31) * 4;
                int jg  = p * 32 + jr;
                float bj = bias ? bias[j0 + jg] : 0.f;
                float4 v = *(const float4*)&stage[jr][m4];
                v.x += bj; v.y += bj; v.z += bj; v.w += bj;
                *(float4*)(Cb + (size_t)jg * 4096 + m4) = v;
            }
        }
        __syncthreads();
    }
}

// ---------------- column stats (max, sumexp) over n for Q -----------------
__global__ __launch_bounds__(256) void qstats_kernel()
{
    __shared__ float red[256];
    int col = blockIdx.x;
    int bb = col >> 6, j = col & 63;
    const float* base = g_qkv + ((size_t)(bb * 192 + j)) * 4096;
    int t = threadIdx.x;
    float v[16];
    float mx = -3.4e38f;
    #pragma unroll
    for (int i = 0; i < 16; i++) { v[i] = base[t + i * 256]; mx = fmaxf(mx, v[i]); }
    red[t] = mx; __syncthreads();
    for (int s2 = 128; s2 > 0; s2 >>= 1) {
        if (t < s2) red[t] = fmaxf(red[t], red[t + s2]);
        __syncthreads();
    }
    mx = red[0]; __syncthreads();
    float sum = 0.f;
    #pragma unroll
    for (int i = 0; i < 16; i++) sum += __expf(v[i] - mx);
    red[t] = sum; __syncthreads();
    for (int s2 = 128; s2 > 0; s2 >>= 1) {
        if (t < s2) red[t] += red[t + s2];
        __syncthreads();
    }
    if (t == 0) { g_M[col] = mx; g_Z[col] = red[0]; }
}

// ---------------- context: C[d,e] = sum_n key[n,d] v[n,e], / Z ------------
__global__ __launch_bounds__(256) void context_kernel()
{
    __shared__ float ks[16][128];
    __shared__ float vs[16][128];
    int bh = blockIdx.x;
    int bb = bh >> 2, h = bh & 3;
    const float* kb = g_qkv + ((size_t)(bb * 192 + 64  + h * 16)) * 4096;
    const float* vb = g_qkv + ((size_t)(bb * 192 + 128 + h * 16)) * 4096;
    int t = threadIdx.x;
    int d = t >> 4, e = t & 15;
    float acc = 0.f;
    for (int n0 = 0; n0 < 4096; n0 += 128) {
        #pragma unroll
        for (int i = 0; i < 2; i++) {
            int idx = t * 2 + i;
            int row = idx >> 5;
            int c4  = (idx & 31) * 4;
            *(float4*)&ks[row][c4] = *(const float4*)(kb + (size_t)row * 4096 + n0 + c4);
            *(float4*)&vs[row][c4] = *(const float4*)(vb + (size_t)row * 4096 + n0 + c4);
        }
        __syncthreads();
        #pragma unroll
        for (int q4 = 0; q4 < 32; q4++) {
            float4 a = *(const float4*)&ks[d][q4 * 4];
            float4 b = *(const float4*)&vs[e][q4 * 4];
            acc += a.x * b.x + a.y * b.y + a.z * b.z + a.w * b.w;
        }
        __syncthreads();
    }
    float z = g_Z[bb * 64 + h * 16 + d];
    g_ctx[(size_t)bh * 256 + d * 16 + e] = acc / z;
}

// ---------------- attn out: ao = exp(q-M) @ ctx, reference reshape folded:
//   pixel  n' = h*1024 + (n>>2),  chan c' = 16*(n&3) + e ; packed hi/lo out
__global__ __launch_bounds__(256) void attnout_kernel()
{
    __shared__ float cs[1024];
    __shared__ float ms[64];
    int bb = blockIdx.x >> 4;
    int nt = blockIdx.x & 15;
    int t  = threadIdx.x;
    int n  = nt * 256 + t;
    if (t < 64) ms[t] = g_M[bb * 64 + t];
    for (int i = t; i < 1024; i += 256) cs[i] = g_ctx[(size_t)bb * 1024 + i];
    __syncthreads();
    const float* qb = g_qkv + (size_t)bb * 192 * 4096 + n;
    int cbase = 16 * (n & 3);
    int pbase = n >> 2;
    for (int h = 0; h < 4; h++) {
        float acc[16];
        #pragma unroll
        for (int e = 0; e < 16; e++) acc[e] = 0.f;
        #pragma unroll
        for (int d = 0; d < 16; d++) {
            int jc = h * 16 + d;
            float qv = __expf(qb[(size_t)jc * 4096] - ms[jc]);
            const float4* crow = (const float4*)&cs[jc * 16];
            #pragma unroll
            for (int e4 = 0; e4 < 4; e4++) {
                float4 cv = crow[e4];
                acc[e4 * 4 + 0] += qv * cv.x;
                acc[e4 * 4 + 1] += qv * cv.y;
                acc[e4 * 4 + 2] += qv * cv.z;
                acc[e4 * 4 + 3] += qv * cv.w;
            }
        }
        int np = h * 1024 + pbase;
        #pragma unroll
        for (int e = 0; e < 16; e++)
            g_aohl[((size_t)(bb * 64 + cbase + e)) * 4096 + np] = packhl(acc[e]);
    }
}

// ---------------- launch ---------------------------------------------------
extern "C" void kernel_launch(void* const* d_in, const int* in_sizes, int n_in,
                              void* d_out, int out_size)
{
    const float* x   = (const float*)d_in[0];
    const float* w3  = (const float*)d_in[1];
    const float* b3  = (const float*)d_in[2];
    const float* w5  = (const float*)d_in[3];
    const float* b5  = (const float*)d_in[4];
    const float* w7  = (const float*)d_in[5];
    const float* b7  = (const float*)d_in[6];
    const float* w9  = (const float*)d_in[7];
    const float* b9  = (const float*)d_in[8];
    const float* w_qkv   = (const float*)d_in[9];
    const float* w_proj  = (const float*)d_in[10];
    const float* b_proj  = (const float*)d_in[11];
    const float* w_final = (const float*)d_in[12];
    const float* b_final = (const float*)d_in[13];
    const float* scale_w = (const float*)d_in[14];
    float* out = (float*)d_out;

    unsigned *yp, *aop;
    float *qkvp, *wcp, *cbp;
    cudaGetSymbolAddress((void**)&yp,   g_yhl);
    cudaGetSymbolAddress((void**)&qkvp, g_qkv);
    cudaGetSymbolAddress((void**)&aop,  g_aohl);
    cudaGetSymbolAddress((void**)&wcp,  g_wc);
    cudaGetSymbolAddress((void**)&cbp,  g_cb);

    // 0. fuse proj+final weights: Wc = scale * Wf @ Wp, cbias
    wcprep_kernel<<<256, 256>>>(w_proj, w_final, b_proj, b_final, scale_w);

    // 1. depthwise conv + bias + residual + relu  -> g_yhl (packed hi/lo)
    dwconv_kernel<<<NB * NDIM, 256>>>(x, w3, b3, w5, b5, w7, b7, w9, b9);

    // 2. QKV GEMM with fused K-softmax epilogue -> g_qkv
    gemm_tc<<<dim3(3, 262144 / 128), 256>>>(yp, w_qkv, nullptr, qkvp,
                                            64, 64L * 4096, 192L * 4096, 1);

    // 3. column stats for Q softmax
    qstats_kernel<<<4096, 256>>>();

    // 4. context = key^T v, folded / Z
    context_kernel<<<256, 256>>>();

    // 5. attention out -> g_aohl (packed hi/lo, scrambled reshape layout)
    attnout_kernel<<<1024, 256>>>();   // <-- ncu capture index 5

    // 6. fused proj+final GEMM: out = Wc @ ao + cbias
    gemm_tc<<<dim3(4, 65536 / 128), 256>>>(aop, wcp, cbp, out,
                                           256, 256L * 4096, 256L * 4096, 0);
}